// round 15
// baseline (speedup 1.0000x reference)
#include <cuda_runtime.h>
#include <cuda_fp16.h>
#include <cstdint>

// ---------------- problem constants ----------------
constexpr int B    = 2;
constexpr int N    = 6400;
constexpr int E    = 256;
constexpr int CAMS = 6;
constexpr int LVLS = 4;
constexpr int BN_PTS = B * N;          // 12800
__device__ constexpr int HGT[LVLS]  = {64, 32, 16, 8};
__device__ constexpr int WID[LVLS]  = {176, 88, 44, 22};
__device__ constexpr int LOFF[LVLS] = {0, 11264, 14080, 14784};
__device__ constexpr int LHW[LVLS]  = {11264, 2816, 704, 176};
constexpr int TOTHW = 14960;           // sum of H*W

// ---------------- device scratch ----------------
__device__ __half g_featT[(size_t)B * CAMS * TOTHW * E];  // ~92 MB fp16 [b,c,hw,E]
__device__ __half g_aggH[(size_t)BN_PTS * E];
__device__ __half g_xh[(size_t)BN_PTS * E];
__device__ __half g_vpH[E * E];
__device__ __half g_opH[E * E];

// ---------------- helpers ----------------
__device__ __forceinline__ uint32_t smem_u32(const void* p) {
    return (uint32_t)__cvta_generic_to_shared(p);
}
__device__ __forceinline__ void ldmx4(unsigned r[4], uint32_t addr) {
    asm volatile("ldmatrix.sync.aligned.m8n8.x4.shared.b16 {%0,%1,%2,%3}, [%4];"
                 : "=r"(r[0]), "=r"(r[1]), "=r"(r[2]), "=r"(r[3]) : "r"(addr));
}
__device__ __forceinline__ void mma16816(float d[4], const unsigned a[4], const unsigned b[2]) {
    asm volatile("mma.sync.aligned.m16n8k16.row.col.f32.f16.f16.f32 "
                 "{%0,%1,%2,%3}, {%4,%5,%6,%7}, {%8,%9}, {%0,%1,%2,%3};"
                 : "+f"(d[0]), "+f"(d[1]), "+f"(d[2]), "+f"(d[3])
                 : "r"(a[0]), "r"(a[1]), "r"(a[2]), "r"(a[3]), "r"(b[0]), "r"(b[1]));
}
__device__ __forceinline__ void cp16(uint32_t dst, const void* src) {
    asm volatile("cp.async.cg.shared.global [%0], [%1], 16;" :: "r"(dst), "l"(src));
}
__device__ __forceinline__ void cp_commit() {
    asm volatile("cp.async.commit_group;");
}
template <int NN>
__device__ __forceinline__ void cp_wait() {
    asm volatile("cp.async.wait_group %0;" :: "n"(NN));
}

// ---------------- 1) merged transpose (+ weight convert tail blocks) -------
__global__ __launch_bounds__(256) void transpose_all_kernel(
        const float* __restrict__ f0, const float* __restrict__ f1,
        const float* __restrict__ f2, const float* __restrict__ f3,
        const float* __restrict__ vp_w, const float* __restrict__ op_w) {
    int bc  = blockIdx.y;
    int idx = blockIdx.x;
    int t   = threadIdx.x;

    if (idx >= 936) {
        if (bc != 0) return;
        int w = idx - 936;                   // 0..63
        int base = w * 1024 + t * 4;
        float4 v = *(const float4*)(vp_w + base);
        float4 o = *(const float4*)(op_w + base);
        __half2 a0 = __floats2half2_rn(v.x, v.y);
        __half2 a1 = __floats2half2_rn(v.z, v.w);
        __half2 b0 = __floats2half2_rn(o.x, o.y);
        __half2 b1 = __floats2half2_rn(o.z, o.w);
        uint2 pa, pb;
        pa.x = *(const unsigned*)&a0; pa.y = *(const unsigned*)&a1;
        pb.x = *(const unsigned*)&b0; pb.y = *(const unsigned*)&b1;
        *(uint2*)(g_vpH + base) = pa;
        *(uint2*)(g_opH + base) = pb;
        return;
    }

    int l, r;
    const float* fsrc;
    if (idx < 704)      { l = 0; r = idx;       fsrc = f0; }
    else if (idx < 880) { l = 1; r = idx - 704; fsrc = f1; }
    else if (idx < 924) { l = 2; r = idx - 880; fsrc = f2; }
    else                { l = 3; r = idx - 924; fsrc = f3; }

    const int HW  = LHW[l];
    const int OFF = LOFF[l];
    int e0  = (r & 3) * 64;
    int hw0 = (r >> 2) * 64;

    const float* src = fsrc + (size_t)bc * E * HW;
    __half* dst = g_featT + ((size_t)bc * TOTHW + OFF) * E;

    __shared__ float tile[64][65];        // [e][hw]

    #pragma unroll
    for (int i = 0; i < 4; i++) {
        int idx2 = t + i * 256;
        int er   = idx2 >> 4;
        int c4   = idx2 & 15;
        int hw   = hw0 + c4 * 4;
        if (hw < HW) {
            float4 v = *(const float4*)(src + (size_t)(e0 + er) * HW + hw);
            tile[er][c4 * 4 + 0] = v.x;
            tile[er][c4 * 4 + 1] = v.y;
            tile[er][c4 * 4 + 2] = v.z;
            tile[er][c4 * 4 + 3] = v.w;
        }
    }
    __syncthreads();

    #pragma unroll
    for (int i = 0; i < 2; i++) {
        int idx2 = t + i * 256;
        int hwl  = idx2 >> 3;
        int seg  = idx2 & 7;
        int hw   = hw0 + hwl;
        if (hw < HW) {
            __half2 v0 = __floats2half2_rn(tile[seg * 8 + 0][hwl], tile[seg * 8 + 1][hwl]);
            __half2 v1 = __floats2half2_rn(tile[seg * 8 + 2][hwl], tile[seg * 8 + 3][hwl]);
            __half2 v2 = __floats2half2_rn(tile[seg * 8 + 4][hwl], tile[seg * 8 + 5][hwl]);
            __half2 v3 = __floats2half2_rn(tile[seg * 8 + 6][hwl], tile[seg * 8 + 7][hwl]);
            uint4 pk;
            pk.x = *(const unsigned*)&v0;
            pk.y = *(const unsigned*)&v1;
            pk.z = *(const unsigned*)&v2;
            pk.w = *(const unsigned*)&v3;
            *(uint4*)(dst + (size_t)hw * E + e0 + seg * 8) = pk;
        }
    }
}

// ---------------- 2+3) fused prep + gather, 4 warps per point --------------
// Balanced mapping: warp sub s handles pairs (cam c, level (c+s)&3), c=0..5.
// Max level-0 pairs per warp = 2 (was 3 with the cam/level-half split).
__global__ __launch_bounds__(256) void aggregate_kernel(
                            const float* __restrict__ instf,
                            const float* __restrict__ anchor,
                            const float* __restrict__ proj,
                            const float* __restrict__ attn_w,
                            const float* __restrict__ attn_b) {
    int t    = threadIdx.x;
    int warp = t >> 5;
    int lane = t & 31;
    int pt   = warp >> 2;             // point-within-block 0..1
    int sub  = warp & 3;              // sub-warp 0..3
    int p    = blockIdx.x * 2 + pt;
    int b    = p / N;

    __shared__ float s_logit[2][24];
    __shared__ float s_uv[2][12];
    __shared__ float s_red[2][3][256];

    // ---- prep: each warp computes logits for its 6 (cam, lvl) pairs ----
    {
        const float* ifp = instf + (size_t)p * E;
        float v[8];
        #pragma unroll
        for (int k = 0; k < 8; k++) v[k] = ifp[k * 32 + lane];

        #pragma unroll
        for (int c = 0; c < CAMS; c++) {
            int lvl = (c + sub) & 3;
            int cl  = c * 4 + lvl;
            const float* w = attn_w + cl * E;
            float s = 0.f;
            #pragma unroll
            for (int k = 0; k < 8; k++) s = fmaf(v[k], w[k * 32 + lane], s);
            #pragma unroll
            for (int o = 16; o; o >>= 1) s += __shfl_xor_sync(0xffffffffu, s, o);
            if (lane == 0) s_logit[pt][cl] = s + attn_b[cl];
        }

        if (sub == 0 && lane < 16) {
            float ax = anchor[(size_t)p * 11 + 0];
            float ay = anchor[(size_t)p * 11 + 1];
            float az = anchor[(size_t)p * 11 + 2];
            float sx = 1.0f / (1.0f + __expf(-ax));
            float sy = 1.0f / (1.0f + __expf(-ay));
            float sz = 1.0f / (1.0f + __expf(-az));
            float X = sx * 102.4f - 51.2f;
            float Y = sy * 102.4f - 51.2f;
            float Z = sz * 8.0f   - 5.0f;
            if (lane < CAMS) {
                const float* P = proj + ((size_t)b * CAMS + lane) * 16;
                float c0 = P[0]  * X + P[1]  * Y + P[2]  * Z + P[3];
                float c1 = P[4]  * X + P[5]  * Y + P[6]  * Z + P[7];
                float c2 = P[8]  * X + P[9]  * Y + P[10] * Z + P[11];
                float d  = fmaxf(c2, 0.0001f);
                s_uv[pt][lane * 2 + 0] = c0 / d;
                s_uv[pt][lane * 2 + 1] = c1 / d;
            }
        }
    }
    __syncthreads();

    // ---- gather: 6 pairs per warp (one level per cam), branch-free corners
    float acc[8] = {0.f, 0.f, 0.f, 0.f, 0.f, 0.f, 0.f, 0.f};

    #pragma unroll
    for (int c = 0; c < CAMS; c++) {
        int lvl = (c + sub) & 3;
        float x = s_uv[pt][c * 2 + 0];
        float y = s_uv[pt][c * 2 + 1];
        const int Wl = WID[lvl], Hl = HGT[lvl], off = LOFF[lvl];
        // uniform fully-OOB test
        if (x <= -1.f || x >= (float)Wl || y <= -1.f || y >= (float)Hl) continue;

        float x0 = floorf(x), y0 = floorf(y);
        float wx1 = x - x0, wx0 = 1.0f - wx1;
        float wy1 = y - y0, wy0 = 1.0f - wy1;
        int xi = (int)x0, yi = (int)y0;
        const __half* base = g_featT + ((size_t)b * CAMS + c) * TOTHW * E;

        float l0 = s_logit[pt][c * 4 + 0], l1 = s_logit[pt][c * 4 + 1];
        float l2 = s_logit[pt][c * 4 + 2], l3 = s_logit[pt][c * 4 + 3];
        float mx = fmaxf(fmaxf(l0, l1), fmaxf(l2, l3));
        float e0 = __expf(l0 - mx), e1 = __expf(l1 - mx);
        float e2 = __expf(l2 - mx), e3 = __expf(l3 - mx);
        float inv = 1.0f / (e0 + e1 + e2 + e3);
        float el = (lvl == 0) ? e0 : (lvl == 1) ? e1 : (lvl == 2) ? e2 : e3;
        float wa = el * inv;

        float vx0 = (xi >= 0)          ? 1.f : 0.f;
        float vx1 = (xi + 1 <= Wl - 1) ? 1.f : 0.f;
        float vy0 = (yi >= 0)          ? 1.f : 0.f;
        float vy1 = (yi + 1 <= Hl - 1) ? 1.f : 0.f;
        int x0c = max(xi, 0);
        int x1c = min(xi + 1, Wl - 1);
        int y0c = max(yi, 0);
        int y1c = min(yi + 1, Hl - 1);

        float w00 = wa * wx0 * wy0 * vx0 * vy0;
        float w10 = wa * wx1 * wy0 * vx1 * vy0;
        float w01 = wa * wx0 * wy1 * vx0 * vy1;
        float w11 = wa * wx1 * wy1 * vx1 * vy1;

        const __half* r0 = base + ((size_t)(off + y0c * Wl)) * E + lane * 8;
        const __half* r1 = base + ((size_t)(off + y1c * Wl)) * E + lane * 8;

        uint4 q00 = *(const uint4*)(r0 + (size_t)x0c * E);
        uint4 q10 = *(const uint4*)(r0 + (size_t)x1c * E);
        uint4 q01 = *(const uint4*)(r1 + (size_t)x0c * E);
        uint4 q11 = *(const uint4*)(r1 + (size_t)x1c * E);

        const __half2* h00 = (const __half2*)&q00;
        const __half2* h10 = (const __half2*)&q10;
        const __half2* h01 = (const __half2*)&q01;
        const __half2* h11 = (const __half2*)&q11;
        #pragma unroll
        for (int q = 0; q < 4; q++) {
            float2 f00 = __half22float2(h00[q]);
            float2 f10 = __half22float2(h10[q]);
            float2 f01 = __half22float2(h01[q]);
            float2 f11 = __half22float2(h11[q]);
            acc[q * 2 + 0] = fmaf(w00, f00.x, fmaf(w10, f10.x,
                             fmaf(w01, f01.x, fmaf(w11, f11.x, acc[q * 2 + 0]))));
            acc[q * 2 + 1] = fmaf(w00, f00.y, fmaf(w10, f10.y,
                             fmaf(w01, f01.y, fmaf(w11, f11.y, acc[q * 2 + 1]))));
        }
    }

    // ---- merge 4 partial sums per point ----
    if (sub != 0) {
        *(float4*)(&s_red[pt][sub - 1][lane * 8 + 0]) = make_float4(acc[0], acc[1], acc[2], acc[3]);
        *(float4*)(&s_red[pt][sub - 1][lane * 8 + 4]) = make_float4(acc[4], acc[5], acc[6], acc[7]);
    }
    __syncthreads();
    if (sub == 0) {
        #pragma unroll
        for (int s = 0; s < 3; s++) {
            float4 r0 = *(const float4*)(&s_red[pt][s][lane * 8 + 0]);
            float4 r1 = *(const float4*)(&s_red[pt][s][lane * 8 + 4]);
            acc[0] += r0.x; acc[1] += r0.y; acc[2] += r0.z; acc[3] += r0.w;
            acc[4] += r1.x; acc[5] += r1.y; acc[6] += r1.z; acc[7] += r1.w;
        }
        __half2 o0 = __floats2half2_rn(acc[0], acc[1]);
        __half2 o1 = __floats2half2_rn(acc[2], acc[3]);
        __half2 o2 = __floats2half2_rn(acc[4], acc[5]);
        __half2 o3 = __floats2half2_rn(acc[6], acc[7]);
        uint4 pk;
        pk.x = *(const unsigned*)&o0; pk.y = *(const unsigned*)&o1;
        pk.z = *(const unsigned*)&o2; pk.w = *(const unsigned*)&o3;
        *(uint4*)(g_aggH + (size_t)p * E + lane * 8) = pk;
    }
}

// ---------------- 4) fp16 tensor-core GEMM, 64x64 tiles, cp.async ----------
// MODE 0: A=g_aggH, W=g_vpH,  out = half(acc + vp_b[n] + instf[m][n]) -> g_xh
// MODE 1: A=g_xh,   W=g_opH,  out = float(acc + op_b[n])              -> Cout
// 256 threads = 8 warps (4x2), warp tile 16x32, grid 800 blocks.
template <int MODE>
__global__ __launch_bounds__(256, 4) void gemm_h_kernel(
        const float* __restrict__ bias,
        const float* __restrict__ instf,
        float* __restrict__ Cout) {
    constexpr int K = 256;
    constexpr int NT = 4;              // K / 64
    const __half* A = (MODE == 0) ? g_aggH : g_xh;
    const __half* W = (MODE == 0) ? g_vpH  : g_opH;

    __shared__ __half sA[2][64 * 64];
    __shared__ __half sB[2][64 * 64];

    int bm = blockIdx.x * 64;
    int bn = blockIdx.y * 64;
    int t  = threadIdx.x;
    int warp = t >> 5, lane = t & 31;
    int wm = warp >> 1, wn = warp & 1;   // 4 x 2 warps; warp tile 16 x 32

    auto swz = [](int row, int chunk) { return row * 64 + ((chunk ^ (row & 7)) << 3); };

    auto load_stage = [&](int k0, int buf) {
        #pragma unroll
        for (int i = 0; i < 2; i++) {
            int c = t + i * 256;               // 0..511
            int row = c >> 3, ch = c & 7;
            cp16(smem_u32(&sA[buf][swz(row, ch)]),
                 A + (size_t)(bm + row) * K + k0 + ch * 8);
            cp16(smem_u32(&sB[buf][swz(row, ch)]),
                 W + (size_t)(bn + row) * K + k0 + ch * 8);
        }
        cp_commit();
    };

    float acc[4][4];
    #pragma unroll
    for (int j = 0; j < 4; j++)
        #pragma unroll
        for (int q = 0; q < 4; q++) acc[j][q] = 0.f;

    int lidx = lane & 7, lg = lane >> 3;

    load_stage(0, 0);

    #pragma unroll
    for (int kt = 0; kt < NT; kt++) {
        int buf = kt & 1;
        if (kt + 1 < NT) load_stage((kt + 1) * 64, buf ^ 1);
        if (kt + 1 < NT) cp_wait<1>(); else cp_wait<0>();
        __syncthreads();

        #pragma unroll
        for (int ks = 0; ks < 4; ks++) {
            int kc = ks * 2;
            unsigned af[4], bf[2][4];
            {
                int row = wm * 16 + (lg & 1) * 8 + lidx;
                int ch  = kc + (lg >> 1);
                ldmx4(af, smem_u32(&sA[buf][swz(row, ch)]));
            }
            #pragma unroll
            for (int h = 0; h < 2; h++) {
                int row = wn * 32 + h * 16 + ((lg >> 1) & 1) * 8 + lidx;
                int ch  = kc + (lg & 1);
                ldmx4(bf[h], smem_u32(&sB[buf][swz(row, ch)]));
            }
            #pragma unroll
            for (int nt = 0; nt < 4; nt++)
                mma16816(acc[nt], af, bf[nt >> 1] + (nt & 1) * 2);
        }
        __syncthreads();
    }

    int rbase = bm + wm * 16 + (lane >> 2);
    int cbase = bn + wn * 32 + (lane & 3) * 2;
    #pragma unroll
    for (int nt = 0; nt < 4; nt++) {
        int col = cbase + nt * 8;
        float b0 = bias[col], b1 = bias[col + 1];
        #pragma unroll
        for (int h = 0; h < 2; h++) {
            int row = rbase + h * 8;
            float v0 = acc[nt][h * 2 + 0] + b0;
            float v1 = acc[nt][h * 2 + 1] + b1;
            if (MODE == 0) {
                v0 += instf[(size_t)row * 256 + col];
                v1 += instf[(size_t)row * 256 + col + 1];
                __half2 hv = __floats2half2_rn(v0, v1);
                *(__half2*)(g_xh + (size_t)row * 256 + col) = hv;
            } else {
                *(float2*)(Cout + (size_t)row * 256 + col) = make_float2(v0, v1);
            }
        }
    }
}

// ---------------- launch ----------------
extern "C" void kernel_launch(void* const* d_in, const int* in_sizes, int n_in,
                              void* d_out, int out_size) {
    const float* instf  = (const float*)d_in[0];
    const float* anchor = (const float*)d_in[1];
    const float* proj   = (const float*)d_in[2];
    const float* f0     = (const float*)d_in[3];
    const float* f1     = (const float*)d_in[4];
    const float* f2     = (const float*)d_in[5];
    const float* f3     = (const float*)d_in[6];
    const float* attn_w = (const float*)d_in[7];
    const float* attn_b = (const float*)d_in[8];
    const float* vp_w   = (const float*)d_in[9];
    const float* vp_b   = (const float*)d_in[10];
    const float* op_w   = (const float*)d_in[11];
    const float* op_b   = (const float*)d_in[12];
    float* out = (float*)d_out;

    transpose_all_kernel<<<dim3(1000, B * CAMS), 256>>>(f0, f1, f2, f3, vp_w, op_w);

    aggregate_kernel<<<BN_PTS / 2, 256>>>(instf, anchor, proj, attn_w, attn_b);

    dim3 gg(BN_PTS / 64, 256 / 64);
    gemm_h_kernel<0><<<gg, 256>>>(vp_b, instf, out);
    gemm_h_kernel<1><<<gg, 256>>>(op_b, nullptr, out);
}

// round 16
// speedup vs baseline: 1.0203x; 1.0203x over previous
#include <cuda_runtime.h>
#include <cuda_fp16.h>
#include <cstdint>

// ---------------- problem constants ----------------
constexpr int B    = 2;
constexpr int N    = 6400;
constexpr int E    = 256;
constexpr int CAMS = 6;
constexpr int LVLS = 4;
constexpr int BN_PTS = B * N;          // 12800
__device__ constexpr int HGT[LVLS]  = {64, 32, 16, 8};
__device__ constexpr int WID[LVLS]  = {176, 88, 44, 22};
__device__ constexpr int LOFF[LVLS] = {0, 11264, 14080, 14784};
__device__ constexpr int LHW[LVLS]  = {11264, 2816, 704, 176};
constexpr int TOTHW = 14960;           // sum of H*W

// ---------------- device scratch ----------------
__device__ __half g_featT[(size_t)B * CAMS * TOTHW * E];  // ~92 MB fp16 [b,c,hw,E]
__device__ __half g_aggH[(size_t)BN_PTS * E];
__device__ __half g_xh[(size_t)BN_PTS * E];
__device__ __half g_vpH[E * E];
__device__ __half g_opH[E * E];

// ---------------- helpers ----------------
__device__ __forceinline__ uint32_t smem_u32(const void* p) {
    return (uint32_t)__cvta_generic_to_shared(p);
}
__device__ __forceinline__ void ldmx4(unsigned r[4], uint32_t addr) {
    asm volatile("ldmatrix.sync.aligned.m8n8.x4.shared.b16 {%0,%1,%2,%3}, [%4];"
                 : "=r"(r[0]), "=r"(r[1]), "=r"(r[2]), "=r"(r[3]) : "r"(addr));
}
__device__ __forceinline__ void mma16816(float d[4], const unsigned a[4], const unsigned b[2]) {
    asm volatile("mma.sync.aligned.m16n8k16.row.col.f32.f16.f16.f32 "
                 "{%0,%1,%2,%3}, {%4,%5,%6,%7}, {%8,%9}, {%0,%1,%2,%3};"
                 : "+f"(d[0]), "+f"(d[1]), "+f"(d[2]), "+f"(d[3])
                 : "r"(a[0]), "r"(a[1]), "r"(a[2]), "r"(a[3]), "r"(b[0]), "r"(b[1]));
}
__device__ __forceinline__ void cp16(uint32_t dst, const void* src) {
    asm volatile("cp.async.cg.shared.global [%0], [%1], 16;" :: "r"(dst), "l"(src));
}
__device__ __forceinline__ void cp_commit() {
    asm volatile("cp.async.commit_group;");
}
template <int NN>
__device__ __forceinline__ void cp_wait() {
    asm volatile("cp.async.wait_group %0;" :: "n"(NN));
}

// ---------------- 1) merged transpose (+ weight convert tail blocks) -------
__global__ __launch_bounds__(256) void transpose_all_kernel(
        const float* __restrict__ f0, const float* __restrict__ f1,
        const float* __restrict__ f2, const float* __restrict__ f3,
        const float* __restrict__ vp_w, const float* __restrict__ op_w) {
    int bc  = blockIdx.y;
    int idx = blockIdx.x;
    int t   = threadIdx.x;

    if (idx >= 936) {
        if (bc != 0) return;
        int w = idx - 936;                   // 0..63
        int base = w * 1024 + t * 4;
        float4 v = *(const float4*)(vp_w + base);
        float4 o = *(const float4*)(op_w + base);
        __half2 a0 = __floats2half2_rn(v.x, v.y);
        __half2 a1 = __floats2half2_rn(v.z, v.w);
        __half2 b0 = __floats2half2_rn(o.x, o.y);
        __half2 b1 = __floats2half2_rn(o.z, o.w);
        uint2 pa, pb;
        pa.x = *(const unsigned*)&a0; pa.y = *(const unsigned*)&a1;
        pb.x = *(const unsigned*)&b0; pb.y = *(const unsigned*)&b1;
        *(uint2*)(g_vpH + base) = pa;
        *(uint2*)(g_opH + base) = pb;
        return;
    }

    int l, r;
    const float* fsrc;
    if (idx < 704)      { l = 0; r = idx;       fsrc = f0; }
    else if (idx < 880) { l = 1; r = idx - 704; fsrc = f1; }
    else if (idx < 924) { l = 2; r = idx - 880; fsrc = f2; }
    else                { l = 3; r = idx - 924; fsrc = f3; }

    const int HW  = LHW[l];
    const int OFF = LOFF[l];
    int e0  = (r & 3) * 64;
    int hw0 = (r >> 2) * 64;

    const float* src = fsrc + (size_t)bc * E * HW;
    __half* dst = g_featT + ((size_t)bc * TOTHW + OFF) * E;

    __shared__ float tile[64][65];        // [e][hw]

    #pragma unroll
    for (int i = 0; i < 4; i++) {
        int idx2 = t + i * 256;
        int er   = idx2 >> 4;
        int c4   = idx2 & 15;
        int hw   = hw0 + c4 * 4;
        if (hw < HW) {
            float4 v = *(const float4*)(src + (size_t)(e0 + er) * HW + hw);
            tile[er][c4 * 4 + 0] = v.x;
            tile[er][c4 * 4 + 1] = v.y;
            tile[er][c4 * 4 + 2] = v.z;
            tile[er][c4 * 4 + 3] = v.w;
        }
    }
    __syncthreads();

    #pragma unroll
    for (int i = 0; i < 2; i++) {
        int idx2 = t + i * 256;
        int hwl  = idx2 >> 3;
        int seg  = idx2 & 7;
        int hw   = hw0 + hwl;
        if (hw < HW) {
            __half2 v0 = __floats2half2_rn(tile[seg * 8 + 0][hwl], tile[seg * 8 + 1][hwl]);
            __half2 v1 = __floats2half2_rn(tile[seg * 8 + 2][hwl], tile[seg * 8 + 3][hwl]);
            __half2 v2 = __floats2half2_rn(tile[seg * 8 + 4][hwl], tile[seg * 8 + 5][hwl]);
            __half2 v3 = __floats2half2_rn(tile[seg * 8 + 6][hwl], tile[seg * 8 + 7][hwl]);
            uint4 pk;
            pk.x = *(const unsigned*)&v0;
            pk.y = *(const unsigned*)&v1;
            pk.z = *(const unsigned*)&v2;
            pk.w = *(const unsigned*)&v3;
            *(uint4*)(dst + (size_t)hw * E + e0 + seg * 8) = pk;
        }
    }
}

// ---------------- 2+3) fused prep + gather, 4 warps per point (R14) --------
// Warp (hf, lh): cams [3hf,3hf+3) x levels [2lh,2lh+2); branch-free corners.
__global__ __launch_bounds__(256) void aggregate_kernel(
                            const float* __restrict__ instf,
                            const float* __restrict__ anchor,
                            const float* __restrict__ proj,
                            const float* __restrict__ attn_w,
                            const float* __restrict__ attn_b) {
    int t    = threadIdx.x;
    int warp = t >> 5;
    int lane = t & 31;
    int pt   = warp >> 2;             // point-within-block 0..1
    int sub  = warp & 3;              // sub-warp 0..3
    int hf   = sub >> 1;              // cam-half
    int lh   = sub & 1;               // level-half
    int p    = blockIdx.x * 2 + pt;
    int b    = p / N;

    __shared__ float s_logit[2][24];
    __shared__ float s_uv[2][12];
    __shared__ float s_red[2][3][256];

    // ---- prep: each warp computes its 6 logits ----
    {
        const float* ifp = instf + (size_t)p * E;
        float v[8];
        #pragma unroll
        for (int k = 0; k < 8; k++) v[k] = ifp[k * 32 + lane];

        #pragma unroll
        for (int j = 0; j < 6; j++) {
            int cam = hf * 3 + j / 2;
            int lvl = lh * 2 + (j & 1);
            int cl  = cam * 4 + lvl;
            const float* w = attn_w + cl * E;
            float s = 0.f;
            #pragma unroll
            for (int k = 0; k < 8; k++) s = fmaf(v[k], w[k * 32 + lane], s);
            #pragma unroll
            for (int o = 16; o; o >>= 1) s += __shfl_xor_sync(0xffffffffu, s, o);
            if (lane == 0) s_logit[pt][cl] = s + attn_b[cl];
        }

        if (sub == 0 && lane < 16) {
            float ax = anchor[(size_t)p * 11 + 0];
            float ay = anchor[(size_t)p * 11 + 1];
            float az = anchor[(size_t)p * 11 + 2];
            float sx = 1.0f / (1.0f + __expf(-ax));
            float sy = 1.0f / (1.0f + __expf(-ay));
            float sz = 1.0f / (1.0f + __expf(-az));
            float X = sx * 102.4f - 51.2f;
            float Y = sy * 102.4f - 51.2f;
            float Z = sz * 8.0f   - 5.0f;
            if (lane < CAMS) {
                const float* P = proj + ((size_t)b * CAMS + lane) * 16;
                float c0 = P[0]  * X + P[1]  * Y + P[2]  * Z + P[3];
                float c1 = P[4]  * X + P[5]  * Y + P[6]  * Z + P[7];
                float c2 = P[8]  * X + P[9]  * Y + P[10] * Z + P[11];
                float d  = fmaxf(c2, 0.0001f);
                s_uv[pt][lane * 2 + 0] = c0 / d;
                s_uv[pt][lane * 2 + 1] = c1 / d;
            }
        }
    }
    __syncthreads();

    // ---- gather: 3 cams x 2 levels per warp, branch-free corners ----
    float acc[8] = {0.f, 0.f, 0.f, 0.f, 0.f, 0.f, 0.f, 0.f};

    #pragma unroll
    for (int c3 = 0; c3 < 3; c3++) {
        int cam = hf * 3 + c3;
        float x = s_uv[pt][cam * 2 + 0];
        float y = s_uv[pt][cam * 2 + 1];
        float x0 = floorf(x), y0 = floorf(y);
        float wx1 = x - x0, wx0 = 1.0f - wx1;
        float wy1 = y - y0, wy0 = 1.0f - wy1;
        int xi = (int)x0, yi = (int)y0;
        const __half* base = g_featT + ((size_t)b * CAMS + cam) * TOTHW * E;

        float l0 = s_logit[pt][cam * 4 + 0], l1 = s_logit[pt][cam * 4 + 1];
        float l2 = s_logit[pt][cam * 4 + 2], l3 = s_logit[pt][cam * 4 + 3];
        float mx = fmaxf(fmaxf(l0, l1), fmaxf(l2, l3));
        float e0 = __expf(l0 - mx), e1 = __expf(l1 - mx);
        float e2 = __expf(l2 - mx), e3 = __expf(l3 - mx);
        float inv = 1.0f / (e0 + e1 + e2 + e3);
        float wsm[2];
        wsm[0] = (lh ? e2 : e0) * inv;
        wsm[1] = (lh ? e3 : e1) * inv;

        #pragma unroll
        for (int l2i = 0; l2i < 2; l2i++) {
            int lvl = lh * 2 + l2i;
            const int Wl = WID[lvl], Hl = HGT[lvl], off = LOFF[lvl];
            if (x <= -1.f || x >= (float)Wl || y <= -1.f || y >= (float)Hl) continue;
            float wa = wsm[l2i];

            float vx0 = (xi >= 0)          ? 1.f : 0.f;
            float vx1 = (xi + 1 <= Wl - 1) ? 1.f : 0.f;
            float vy0 = (yi >= 0)          ? 1.f : 0.f;
            float vy1 = (yi + 1 <= Hl - 1) ? 1.f : 0.f;
            int x0c = max(xi, 0);
            int x1c = min(xi + 1, Wl - 1);
            int y0c = max(yi, 0);
            int y1c = min(yi + 1, Hl - 1);

            float w00 = wa * wx0 * wy0 * vx0 * vy0;
            float w10 = wa * wx1 * wy0 * vx1 * vy0;
            float w01 = wa * wx0 * wy1 * vx0 * vy1;
            float w11 = wa * wx1 * wy1 * vx1 * vy1;

            const __half* r0 = base + ((size_t)(off + y0c * Wl)) * E + lane * 8;
            const __half* r1 = base + ((size_t)(off + y1c * Wl)) * E + lane * 8;

            uint4 q00 = *(const uint4*)(r0 + (size_t)x0c * E);
            uint4 q10 = *(const uint4*)(r0 + (size_t)x1c * E);
            uint4 q01 = *(const uint4*)(r1 + (size_t)x0c * E);
            uint4 q11 = *(const uint4*)(r1 + (size_t)x1c * E);

            const __half2* h00 = (const __half2*)&q00;
            const __half2* h10 = (const __half2*)&q10;
            const __half2* h01 = (const __half2*)&q01;
            const __half2* h11 = (const __half2*)&q11;
            #pragma unroll
            for (int q = 0; q < 4; q++) {
                float2 f00 = __half22float2(h00[q]);
                float2 f10 = __half22float2(h10[q]);
                float2 f01 = __half22float2(h01[q]);
                float2 f11 = __half22float2(h11[q]);
                acc[q * 2 + 0] = fmaf(w00, f00.x, fmaf(w10, f10.x,
                                 fmaf(w01, f01.x, fmaf(w11, f11.x, acc[q * 2 + 0]))));
                acc[q * 2 + 1] = fmaf(w00, f00.y, fmaf(w10, f10.y,
                                 fmaf(w01, f01.y, fmaf(w11, f11.y, acc[q * 2 + 1]))));
            }
        }
    }

    // ---- merge 4 partial sums per point ----
    if (sub != 0) {
        *(float4*)(&s_red[pt][sub - 1][lane * 8 + 0]) = make_float4(acc[0], acc[1], acc[2], acc[3]);
        *(float4*)(&s_red[pt][sub - 1][lane * 8 + 4]) = make_float4(acc[4], acc[5], acc[6], acc[7]);
    }
    __syncthreads();
    if (sub == 0) {
        #pragma unroll
        for (int s = 0; s < 3; s++) {
            float4 r0 = *(const float4*)(&s_red[pt][s][lane * 8 + 0]);
            float4 r1 = *(const float4*)(&s_red[pt][s][lane * 8 + 4]);
            acc[0] += r0.x; acc[1] += r0.y; acc[2] += r0.z; acc[3] += r0.w;
            acc[4] += r1.x; acc[5] += r1.y; acc[6] += r1.z; acc[7] += r1.w;
        }
        __half2 o0 = __floats2half2_rn(acc[0], acc[1]);
        __half2 o1 = __floats2half2_rn(acc[2], acc[3]);
        __half2 o2 = __floats2half2_rn(acc[4], acc[5]);
        __half2 o3 = __floats2half2_rn(acc[6], acc[7]);
        uint4 pk;
        pk.x = *(const unsigned*)&o0; pk.y = *(const unsigned*)&o1;
        pk.z = *(const unsigned*)&o2; pk.w = *(const unsigned*)&o3;
        *(uint4*)(g_aggH + (size_t)p * E + lane * 8) = pk;
    }
}

// ---------------- 4) fp16 tensor-core GEMM, 64x64 tiles, cp.async ----------
// MODE 0: A=g_aggH, W=g_vpH,  out = half(acc + vp_b[n] + instf[m][n]) -> g_xh
// MODE 1: A=g_xh,   W=g_opH,  out = float(acc + op_b[n])              -> Cout
template <int MODE>
__global__ __launch_bounds__(256, 4) void gemm_h_kernel(
        const float* __restrict__ bias,
        const float* __restrict__ instf,
        float* __restrict__ Cout) {
    constexpr int K = 256;
    constexpr int NT = 4;              // K / 64
    const __half* A = (MODE == 0) ? g_aggH : g_xh;
    const __half* W = (MODE == 0) ? g_vpH  : g_opH;

    __shared__ __half sA[2][64 * 64];
    __shared__ __half sB[2][64 * 64];

    int bm = blockIdx.x * 64;
    int bn = blockIdx.y * 64;
    int t  = threadIdx.x;
    int warp = t >> 5, lane = t & 31;
    int wm = warp >> 1, wn = warp & 1;   // 4 x 2 warps; warp tile 16 x 32

    auto swz = [](int row, int chunk) { return row * 64 + ((chunk ^ (row & 7)) << 3); };

    auto load_stage = [&](int k0, int buf) {
        #pragma unroll
        for (int i = 0; i < 2; i++) {
            int c = t + i * 256;               // 0..511
            int row = c >> 3, ch = c & 7;
            cp16(smem_u32(&sA[buf][swz(row, ch)]),
                 A + (size_t)(bm + row) * K + k0 + ch * 8);
            cp16(smem_u32(&sB[buf][swz(row, ch)]),
                 W + (size_t)(bn + row) * K + k0 + ch * 8);
        }
        cp_commit();
    };

    float acc[4][4];
    #pragma unroll
    for (int j = 0; j < 4; j++)
        #pragma unroll
        for (int q = 0; q < 4; q++) acc[j][q] = 0.f;

    int lidx = lane & 7, lg = lane >> 3;

    load_stage(0, 0);

    #pragma unroll
    for (int kt = 0; kt < NT; kt++) {
        int buf = kt & 1;
        if (kt + 1 < NT) load_stage((kt + 1) * 64, buf ^ 1);
        if (kt + 1 < NT) cp_wait<1>(); else cp_wait<0>();
        __syncthreads();

        #pragma unroll
        for (int ks = 0; ks < 4; ks++) {
            int kc = ks * 2;
            unsigned af[4], bf[2][4];
            {
                int row = wm * 16 + (lg & 1) * 8 + lidx;
                int ch  = kc + (lg >> 1);
                ldmx4(af, smem_u32(&sA[buf][swz(row, ch)]));
            }
            #pragma unroll
            for (int h = 0; h < 2; h++) {
                int row = wn * 32 + h * 16 + ((lg >> 1) & 1) * 8 + lidx;
                int ch  = kc + (lg & 1);
                ldmx4(bf[h], smem_u32(&sB[buf][swz(row, ch)]));
            }
            #pragma unroll
            for (int nt = 0; nt < 4; nt++)
                mma16816(acc[nt], af, bf[nt >> 1] + (nt & 1) * 2);
        }
        __syncthreads();
    }

    int rbase = bm + wm * 16 + (lane >> 2);
    int cbase = bn + wn * 32 + (lane & 3) * 2;
    #pragma unroll
    for (int nt = 0; nt < 4; nt++) {
        int col = cbase + nt * 8;
        float b0 = bias[col], b1 = bias[col + 1];
        #pragma unroll
        for (int h = 0; h < 2; h++) {
            int row = rbase + h * 8;
            float v0 = acc[nt][h * 2 + 0] + b0;
            float v1 = acc[nt][h * 2 + 1] + b1;
            if (MODE == 0) {
                v0 += instf[(size_t)row * 256 + col];
                v1 += instf[(size_t)row * 256 + col + 1];
                __half2 hv = __floats2half2_rn(v0, v1);
                *(__half2*)(g_xh + (size_t)row * 256 + col) = hv;
            } else {
                *(float2*)(Cout + (size_t)row * 256 + col) = make_float2(v0, v1);
            }
        }
    }
}

// ---------------- launch ----------------
extern "C" void kernel_launch(void* const* d_in, const int* in_sizes, int n_in,
                              void* d_out, int out_size) {
    const float* instf  = (const float*)d_in[0];
    const float* anchor = (const float*)d_in[1];
    const float* proj   = (const float*)d_in[2];
    const float* f0     = (const float*)d_in[3];
    const float* f1     = (const float*)d_in[4];
    const float* f2     = (const float*)d_in[5];
    const float* f3     = (const float*)d_in[6];
    const float* attn_w = (const float*)d_in[7];
    const float* attn_b = (const float*)d_in[8];
    const float* vp_w   = (const float*)d_in[9];
    const float* vp_b   = (const float*)d_in[10];
    const float* op_w   = (const float*)d_in[11];
    const float* op_b   = (const float*)d_in[12];
    float* out = (float*)d_out;

    transpose_all_kernel<<<dim3(1000, B * CAMS), 256>>>(f0, f1, f2, f3, vp_w, op_w);

    aggregate_kernel<<<BN_PTS / 2, 256>>>(instf, anchor, proj, attn_w, attn_b);

    dim3 gg(BN_PTS / 64, 256 / 64);
    gemm_h_kernel<0><<<gg, 256>>>(vp_b, instf, out);
    gemm_h_kernel<1><<<gg, 256>>>(op_b, nullptr, out);
}